// round 16
// baseline (speedup 1.0000x reference)
#include <cuda_runtime.h>
#include <cstdint>

#define N_NODES   100000
#define D_FEAT    128
#define HID       64
#define N_SAMPLES 250000

// ---- fixed-point scales (compile-time; glorot bound r=sqrt(6/512)=0.108253) ----
#define SA_    (8.0f / 127.0f)
#define INVSA  (127.0f / 8.0f)
#define INVSAL (256.0f * 127.0f / 8.0f)
#define SB_    (0.10830f / 127.0f)
#define INVSB  (127.0f / 0.10830f)
#define INVSBL (256.0f * 127.0f / 0.10830f)
#define S1_    (SA_ * SB_)
#define S2_    (S1_ / 256.0f)

// Merged per-node table (51.2 MB scratch).
// T[n][ 0: 64] = x1[n]@w1[0:128]   + x2[n]@w1[256:384] + b1   (src half)
// T[n][64:128] = x1[n]@w1[128:256] + x2[n]@w1[384:512]        (dst half)
__device__ float g_T[(size_t)N_NODES * 128];

// Quantized B operand (hi/lo int8). Chunk-major: [c][n 0..127][kk 0..63].
__device__ char g_qBh[4 * 128 * 64];
__device__ char g_qBl[4 * 128 * 64];

__device__ int g_idx_is64;   // 1 if train_sample is int64, 0 if int32

// ---------------- helpers ----------------
__device__ __forceinline__ uint32_t smem_u32(const void* p) {
    uint32_t a;
    asm("{ .reg .u64 t; cvta.to.shared.u64 t, %1; cvt.u32.u64 %0, t; }"
        : "=r"(a) : "l"(p));
    return a;
}
__device__ __forceinline__ void ldmatrix_x4(uint32_t& r0, uint32_t& r1,
                                            uint32_t& r2, uint32_t& r3,
                                            uint32_t addr) {
    asm volatile("ldmatrix.sync.aligned.m8n8.x4.shared.b16 {%0,%1,%2,%3}, [%4];"
                 : "=r"(r0), "=r"(r1), "=r"(r2), "=r"(r3) : "r"(addr));
}
__device__ __forceinline__ void mma_s8(int* d, const uint32_t* a,
                                       uint32_t b0, uint32_t b1) {
    asm volatile(
        "mma.sync.aligned.m16n8k32.row.col.s32.s8.s8.s32 "
        "{%0,%1,%2,%3}, {%4,%5,%6,%7}, {%8,%9}, {%0,%1,%2,%3};"
        : "+r"(d[0]), "+r"(d[1]), "+r"(d[2]), "+r"(d[3])
        : "r"(a[0]), "r"(a[1]), "r"(a[2]), "r"(a[3]), "r"(b0), "r"(b1));
}
// pack 4 s32 -> 4 saturated s8 bytes (little-endian q0..q3)
__device__ __forceinline__ uint32_t pack4(int q0, int q1, int q2, int q3) {
    uint32_t d, t;
    asm("cvt.pack.sat.s8.s32.b32 %0, %1, %2, %3;" : "=r"(t)
        : "r"(q3), "r"(q2), "r"(0));
    asm("cvt.pack.sat.s8.s32.b32 %0, %1, %2, %3;" : "=r"(d)
        : "r"(q1), "r"(q0), "r"(t));
    return d;
}
// quantize one float into (hi, lo) ints; residual via exact fma
__device__ __forceinline__ void quant1(float v, int& qh, int& ql) {
    float fq = rintf(v * INVSA);
    qh = (int)fq;
    float r = fmaf(fq, -SA_, v);
    ql = __float2int_rn(r * INVSAL);
}

// ============================================================================
// Kernel 0: dtype detect (block 0) + B int8 quantize (128 blocks, 1 elem/thr).
// B[c][n][kk] = w1[wrow][wcol], gk = 64c + kk:
//   n<64 : wrow = gk<128 ? gk     : gk+128 ; wcol = n
//   n>=64: wrow = gk<128 ? gk+128 : gk+256 ; wcol = n-64
// ============================================================================
__global__ void prep_kernel(const unsigned int* __restrict__ ts32,
                            const float* __restrict__ w1)
{
    int t = threadIdx.x;

    if (blockIdx.x == 0) {
        __shared__ int nonzero;
        if (t == 0) nonzero = 0;
        __syncthreads();
        unsigned int acc = 0;
#pragma unroll
        for (int i = 0; i < 16; i++) acc |= ts32[2 * (t + 256 * i) + 1];
        if (acc) atomicOr(&nonzero, 1);
        __syncthreads();
        if (t == 0) g_idx_is64 = nonzero ? 0 : 1;
    }

    int idx = blockIdx.x * 256 + t;                // 0..32767
    int c  = idx >> 13;
    int n  = (idx >> 6) & 127;
    int kk = idx & 63;
    int gk = c * 64 + kk;
    int wrow = (n < 64) ? ((gk < 128) ? gk : gk + 128)
                        : ((gk < 128) ? gk + 128 : gk + 256);
    int wcol = n & 63;
    float v = w1[wrow * HID + wcol];
    float fq = rintf(v * INVSB);                  // |v| <= 0.10826 -> |fq| <= 127
    int qh = (int)fq;
    float r = fmaf(fq, -SB_, v);
    int ql = __float2int_rn(r * INVSBL);
    ql = max(-128, min(127, ql));
    g_qBh[idx] = (char)qh;
    g_qBl[idx] = (char)ql;
}

// ============================================================================
// Kernel 1: IMMA precompute GEMM — 3-term s8 fixed point, s32 accumulate.
// D = S1*(qh@qbh) + S2*(qh@qbl + ql@qbh)   [lo*lo dropped, ~5e-5 rel]
// CTA: 256 threads (8 warps), 64M x 128N, K=256 in four 64-chunks
// (2 k32 MMA steps each). Warp tile 32x32 (2x4 m16n8k32).
// A staged int8 hi/lo in smem, 80-byte rows (16B-aligned for ldmatrix,
// banks 20r mod 32 -> conflict-free). B frags direct 32-bit LDGs.
// ============================================================================
#define AQ_STRIDE 80    // bytes per A smem row: 64 data + 16 pad (16B multiple!)

__global__ __launch_bounds__(256, 2)
void precompute_imma_kernel(const float* __restrict__ in1,
                            const float* __restrict__ in2,
                            const float* __restrict__ b1)
{
    __shared__ char Ahi[64 * AQ_STRIDE];
    __shared__ char Alo[64 * AQ_STRIDE];

    const int t      = threadIdx.x;
    const int wid    = t >> 5;
    const int lane   = t & 31;
    const int warp_m = wid & 1;          // 0..1  (32-row halves)
    const int warp_n = wid >> 1;         // 0..3  (32-col quarters)
    const int row0   = blockIdx.x * 64;

    const uint32_t ahi_base = smem_u32(Ahi);
    const uint32_t alo_base = smem_u32(Alo);

    int acc1[2][4][4];    // hi*hi   (scale S1)
    int acc2[2][4][4];    // hi*lo + lo*hi (scale S2)
#pragma unroll
    for (int mt = 0; mt < 2; mt++)
#pragma unroll
        for (int nt = 0; nt < 4; nt++)
#pragma unroll
            for (int r = 0; r < 4; r++) { acc1[mt][nt][r] = 0; acc2[mt][nt][r] = 0; }

    const int lm_row  = lane & 15;            // ldmatrix row within 16-row tile
    const int lm_koff = (lane >> 4) * 16;     // ldmatrix byte k-half

    for (int c = 0; c < 4; c++) {
        if (c) __syncthreads();               // protect smem reuse

        // ---- stage A chunk: 64 rows x 64 k fp32 -> int8 hi/lo ----
        const float* __restrict__ in = (c < 2) ? in1 : in2;
        const int col0 = (c & 1) * 64;
#pragma unroll
        for (int i = 0; i < 4; i++) {
            int linear = t + 256 * i;          // 0..1023 float4 slots
            int r  = linear >> 4;              // row 0..63
            int c4 = linear & 15;              // float4 slot along k
            int grow = row0 + r;
            float4 v = make_float4(0.f, 0.f, 0.f, 0.f);
            if (grow < N_NODES)
                v = *(const float4*)&in[(size_t)grow * D_FEAT + col0 + 4 * c4];
            int h0, l0, h1, l1, h2, l2, h3, l3;
            quant1(v.x, h0, l0); quant1(v.y, h1, l1);
            quant1(v.z, h2, l2); quant1(v.w, h3, l3);
            *(uint32_t*)&Ahi[r * AQ_STRIDE + 4 * c4] = pack4(h0, h1, h2, h3);
            *(uint32_t*)&Alo[r * AQ_STRIDE + 4 * c4] = pack4(l0, l1, l2, l3);
        }
        __syncthreads();

        const uint32_t* __restrict__ Bh = (const uint32_t*)(g_qBh + c * 8192);
        const uint32_t* __restrict__ Bl = (const uint32_t*)(g_qBl + c * 8192);

#pragma unroll
        for (int ks = 0; ks < 2; ks++) {
            const int k0 = ks * 32;            // byte offset along k

            // A fragments: 2 m-tiles x (hi,lo); s8-k32 bytes == b16-k16 bytes
            uint32_t ah[2][4], al[2][4];
#pragma unroll
            for (int mt = 0; mt < 2; mt++) {
                int m = warp_m * 32 + mt * 16 + lm_row;
                uint32_t off = (uint32_t)(m * AQ_STRIDE + k0 + lm_koff);
                ldmatrix_x4(ah[mt][0], ah[mt][1], ah[mt][2], ah[mt][3],
                            ahi_base + off);
                ldmatrix_x4(al[mt][0], al[mt][1], al[mt][2], al[mt][3],
                            alo_base + off);
            }
            // B fragments per n-tile (bounded register pressure)
#pragma unroll
            for (int nt = 0; nt < 4; nt++) {
                int n = warp_n * 32 + nt * 8 + (lane >> 2);
                int base = n * 16 + (k0 >> 2) + (lane & 3);   // uint32 index
                uint32_t bh0 = Bh[base], bh1 = Bh[base + 4];
                uint32_t bl0 = Bl[base], bl1 = Bl[base + 4];
#pragma unroll
                for (int mt = 0; mt < 2; mt++) {
                    mma_s8(acc1[mt][nt], ah[mt], bh0, bh1);   // hi*hi
                    mma_s8(acc2[mt][nt], ah[mt], bl0, bl1);   // hi*lo
                    mma_s8(acc2[mt][nt], al[mt], bh0, bh1);   // lo*hi
                }
            }
        }
    }

    // ---- epilogue: rescale, add bias to cols<64, store float2 pairs ----
    const int crow = lane >> 2;               // 0..7
    const int ccol = (lane & 3) * 2;          // 0,2,4,6
#pragma unroll
    for (int nt = 0; nt < 4; nt++) {
        int col = warp_n * 32 + nt * 8 + ccol;
        float2 bv = make_float2(0.f, 0.f);
        if (col < 64) bv = *(const float2*)&b1[col];
#pragma unroll
        for (int mt = 0; mt < 2; mt++) {
            int m = warp_m * 32 + mt * 16 + crow;
            int grow0 = row0 + m;
            int grow1 = grow0 + 8;
            int* d1 = acc1[mt][nt];
            int* d2 = acc2[mt][nt];
            if (grow0 < N_NODES) {
                float v0 = fmaf(S2_, (float)d2[0], S1_ * (float)d1[0]) + bv.x;
                float v1 = fmaf(S2_, (float)d2[1], S1_ * (float)d1[1]) + bv.y;
                *(float2*)&g_T[(size_t)grow0 * 128 + col] = make_float2(v0, v1);
            }
            if (grow1 < N_NODES) {
                float v2 = fmaf(S2_, (float)d2[2], S1_ * (float)d1[2]) + bv.x;
                float v3 = fmaf(S2_, (float)d2[3], S1_ * (float)d1[3]) + bv.y;
                *(float2*)&g_T[(size_t)grow1 * 128 + col] = make_float2(v2, v3);
            }
        }
    }
}

// ============================================================================
// Kernel 2: gather + head. Half-warp per sample; lane l -> float4 of hidden.
// ============================================================================
__global__ __launch_bounds__(256)
void gather_kernel(const void* __restrict__ ts_raw,
                   const float* __restrict__ w2,
                   float* __restrict__ out, int n)
{
    int hs   = (blockIdx.x * blockDim.x + threadIdx.x) >> 4;
    int lane = threadIdx.x & 15;
    if (hs >= n) return;

    long long src, dst;
    if (g_idx_is64) {
        longlong2 sd = ((const longlong2*)ts_raw)[hs];
        src = sd.x; dst = sd.y;
    } else {
        int2 sd = ((const int2*)ts_raw)[hs];
        src = sd.x; dst = sd.y;
    }
    src = min(max(src, 0LL), (long long)(N_NODES - 1));
    dst = min(max(dst, 0LL), (long long)(N_NODES - 1));

    float4 s = *(const float4*)(g_T + (size_t)src * 128 + 4 * lane);
    float4 d = *(const float4*)(g_T + (size_t)dst * 128 + 64 + 4 * lane);
    float4 w = ((const float4*)w2)[lane];

    float p = fmaxf(s.x + d.x, 0.f) * w.x
            + fmaxf(s.y + d.y, 0.f) * w.y
            + fmaxf(s.z + d.z, 0.f) * w.z
            + fmaxf(s.w + d.w, 0.f) * w.w;

#pragma unroll
    for (int off = 8; off; off >>= 1)
        p += __shfl_xor_sync(0xffffffffu, p, off);

    if (lane == 0) out[hs] = p;
}

// ============================================================================
extern "C" void kernel_launch(void* const* d_in, const int* in_sizes, int n_in,
                              void* d_out, int out_size)
{
    const float* in1 = (const float*)d_in[0];      // (100000,128) f32
    const float* in2 = (const float*)d_in[1];      // (100000,128) f32
    const void*  ts  = d_in[2];                    // (250000,2) int32/int64
    const float* w1  = (const float*)d_in[3];      // (512,64) f32
    const float* b1  = (const float*)d_in[4];      // (64,)   f32
    const float* w2  = (const float*)d_in[5];      // (64,1)  f32
    float*       out = (float*)d_out;              // (250000,1) f32

    (void)in_sizes; (void)n_in; (void)out_size;

    prep_kernel<<<128, 256>>>((const unsigned int*)ts, w1);

    precompute_imma_kernel<<<(N_NODES + 63) / 64, 256>>>(in1, in2, b1);

    int samples_per_block = 256 / 16;   // 16 samples per 256-thread block
    int blocks = (N_SAMPLES + samples_per_block - 1) / samples_per_block;
    gather_kernel<<<blocks, 256>>>(ts, w2, out, N_SAMPLES);
}

// round 17
// speedup vs baseline: 1.5137x; 1.5137x over previous
#include <cuda_runtime.h>
#include <cstdint>

#define N_NODES   100000
#define D_FEAT    128
#define HID       64
#define N_SAMPLES 250000

// Merged per-node table (51.2 MB scratch).
// T[n][ 0: 64] = x1[n]@w1[0:128]   + x2[n]@w1[256:384] + b1   (src half)
// T[n][64:128] = x1[n]@w1[128:256] + x2[n]@w1[384:512]        (dst half)
__device__ float g_T[(size_t)N_NODES * 128];

// B operand, tf32-rounded fp32. Chunk-major: [chunk c][n 0..127][kk 0..63].
__device__ float g_Bt[4 * 128 * 64];

__device__ int g_idx_is64;   // 1 if train_sample is int64, 0 if int32

// ---------------- helpers ----------------
__device__ __forceinline__ uint32_t f2tf32(float f) {
    uint32_t r;
    asm("cvt.rna.tf32.f32 %0, %1;" : "=r"(r) : "f"(f));
    return r;
}
__device__ __forceinline__ void mma_tf32(float& d0, float& d1, float& d2, float& d3,
                                         uint32_t a0, uint32_t a1, uint32_t a2, uint32_t a3,
                                         uint32_t b0, uint32_t b1) {
    asm volatile(
        "mma.sync.aligned.m16n8k8.row.col.f32.tf32.tf32.f32 "
        "{%0,%1,%2,%3}, {%4,%5,%6,%7}, {%8,%9}, {%0,%1,%2,%3};"
        : "+f"(d0), "+f"(d1), "+f"(d2), "+f"(d3)
        : "r"(a0), "r"(a1), "r"(a2), "r"(a3), "r"(b0), "r"(b1));
}

// ============================================================================
// Kernel 0: dtype detect (block 0) + B tf32 convert (128 blocks, 1 elem/thr).
// ============================================================================
__global__ void prep_kernel(const unsigned int* __restrict__ ts32,
                            const float* __restrict__ w1)
{
    int t = threadIdx.x;

    if (blockIdx.x == 0) {
        __shared__ int nonzero;
        if (t == 0) nonzero = 0;
        __syncthreads();
        unsigned int acc = 0;
#pragma unroll
        for (int i = 0; i < 16; i++) acc |= ts32[2 * (t + 256 * i) + 1];
        if (acc) atomicOr(&nonzero, 1);
        __syncthreads();
        if (t == 0) g_idx_is64 = nonzero ? 0 : 1;
    }

    int idx = blockIdx.x * 256 + t;                // 0..32767
    int c  = idx >> 13;
    int n  = (idx >> 6) & 127;
    int kk = idx & 63;
    int gk = c * 64 + kk;
    int wrow = (n < 64) ? ((gk < 128) ? gk : gk + 128)
                        : ((gk < 128) ? gk + 128 : gk + 256);
    int wcol = n & 63;
    g_Bt[idx] = __uint_as_float(f2tf32(w1[wrow * HID + wcol]));
}

// ============================================================================
// Kernel 1: warp-MMA precompute GEMM — tf32 single-term (R13 structure),
// now 2 CTAs/SM (unconfounded occupancy experiment: tile unchanged).
// CTA: 256 threads (8 warps), 128M x 128N, K=256 in four 64-chunks.
// Warp tile 64x32 (4x4 m16n8k8 tiles). A staged fp32 (tf32-rounded) in smem,
// stride-68 rows (conflict-free). B frags direct LDGs (L1-resident table).
// ============================================================================
#define AS_STRIDE 68   // fp32 elems per smem row (64 data + 4 pad)

__global__ __launch_bounds__(256, 2)
void precompute_mma_kernel(const float* __restrict__ in1,
                           const float* __restrict__ in2,
                           const float* __restrict__ b1)
{
    __shared__ float Atf[128 * AS_STRIDE];     // 34816 B -> 2 CTAs/SM fit

    const int t      = threadIdx.x;
    const int wid    = t >> 5;
    const int lane   = t & 31;
    const int warp_m = wid & 1;          // 0..1  (64-row halves)
    const int warp_n = wid >> 1;         // 0..3  (32-col quarters)
    const int row0   = blockIdx.x * 128;

    float acc[4][4][4];
#pragma unroll
    for (int mt = 0; mt < 4; mt++)
#pragma unroll
        for (int nt = 0; nt < 4; nt++)
#pragma unroll
            for (int r = 0; r < 4; r++) acc[mt][nt][r] = 0.f;

    const int arow = lane >> 2;               // 0..7 fragment row component
    const int acol = lane & 3;                // 0..3 fragment col component

    for (int c = 0; c < 4; c++) {
        if (c) __syncthreads();               // protect smem reuse

        // ---- stage A chunk: load fp32, tf32-round, store ----
        const float* __restrict__ in = (c < 2) ? in1 : in2;
        const int col0 = (c & 1) * 64;
#pragma unroll
        for (int i = 0; i < 8; i++) {
            int linear = t + 256 * i;          // 0..2047 float4 slots
            int r  = linear >> 4;              // row 0..127
            int c4 = linear & 15;              // float4 slot along k
            int grow = row0 + r;
            float4 v = make_float4(0.f, 0.f, 0.f, 0.f);
            if (grow < N_NODES)
                v = *(const float4*)&in[(size_t)grow * D_FEAT + col0 + 4 * c4];
            uint4 w;
            w.x = f2tf32(v.x); w.y = f2tf32(v.y);
            w.z = f2tf32(v.z); w.w = f2tf32(v.w);
            *(uint4*)&Atf[r * AS_STRIDE + 4 * c4] = w;
        }
        __syncthreads();

        const uint32_t* __restrict__ Au = (const uint32_t*)Atf;
        const uint32_t* __restrict__ Bu = (const uint32_t*)(g_Bt + c * 8192);

#pragma unroll
        for (int ks = 0; ks < 8; ks++) {
            const int k0 = ks * 8;

            // A fragments: 4 m-tiles, m16n8k8 tf32 layout
            uint32_t a[4][4];
#pragma unroll
            for (int mt = 0; mt < 4; mt++) {
                int row = warp_m * 64 + mt * 16 + arow;
                int base = row * AS_STRIDE + k0 + acol;
                a[mt][0] = Au[base];
                a[mt][1] = Au[base + 8 * AS_STRIDE];
                a[mt][2] = Au[base + 4];
                a[mt][3] = Au[base + 8 * AS_STRIDE + 4];
            }
            // B fragments: 4 n-tiles, direct 32-bit loads (L1 hits)
            uint32_t b[4][2];
#pragma unroll
            for (int nt = 0; nt < 4; nt++) {
                int n = warp_n * 32 + nt * 8 + arow;
                int base = n * 64 + k0 + acol;
                b[nt][0] = Bu[base];
                b[nt][1] = Bu[base + 4];
            }
            // MMA: single tf32 term
#pragma unroll
            for (int mt = 0; mt < 4; mt++)
#pragma unroll
                for (int nt = 0; nt < 4; nt++) {
                    float* d = acc[mt][nt];
                    mma_tf32(d[0], d[1], d[2], d[3],
                             a[mt][0], a[mt][1], a[mt][2], a[mt][3],
                             b[nt][0], b[nt][1]);
                }
        }
    }

    // ---- epilogue: add bias to cols<64, store float2 pairs ----
    const int crow = lane >> 2;               // 0..7
    const int ccol = (lane & 3) * 2;          // 0,2,4,6
#pragma unroll
    for (int nt = 0; nt < 4; nt++) {
        int col = warp_n * 32 + nt * 8 + ccol;
        float2 bv = make_float2(0.f, 0.f);
        if (col < 64) bv = *(const float2*)&b1[col];
#pragma unroll
        for (int mt = 0; mt < 4; mt++) {
            int m = warp_m * 64 + mt * 16 + crow;
            int grow0 = row0 + m;
            int grow1 = grow0 + 8;
            float* d = acc[mt][nt];
            if (grow0 < N_NODES)
                *(float2*)&g_T[(size_t)grow0 * 128 + col] =
                    make_float2(d[0] + bv.x, d[1] + bv.y);
            if (grow1 < N_NODES)
                *(float2*)&g_T[(size_t)grow1 * 128 + col] =
                    make_float2(d[2] + bv.x, d[3] + bv.y);
        }
    }
}

// ============================================================================
// Kernel 2: gather + head. Half-warp per sample; lane l -> float4 of hidden.
// ============================================================================
__global__ __launch_bounds__(256)
void gather_kernel(const void* __restrict__ ts_raw,
                   const float* __restrict__ w2,
                   float* __restrict__ out, int n)
{
    int hs   = (blockIdx.x * blockDim.x + threadIdx.x) >> 4;
    int lane = threadIdx.x & 15;
    if (hs >= n) return;

    long long src, dst;
    if (g_idx_is64) {
        longlong2 sd = ((const longlong2*)ts_raw)[hs];
        src = sd.x; dst = sd.y;
    } else {
        int2 sd = ((const int2*)ts_raw)[hs];
        src = sd.x; dst = sd.y;
    }
    src = min(max(src, 0LL), (long long)(N_NODES - 1));
    dst = min(max(dst, 0LL), (long long)(N_NODES - 1));

    float4 s = *(const float4*)(g_T + (size_t)src * 128 + 4 * lane);
    float4 d = *(const float4*)(g_T + (size_t)dst * 128 + 64 + 4 * lane);
    float4 w = ((const float4*)w2)[lane];

    float p = fmaxf(s.x + d.x, 0.f) * w.x
            + fmaxf(s.y + d.y, 0.f) * w.y
            + fmaxf(s.z + d.z, 0.f) * w.z
            + fmaxf(s.w + d.w, 0.f) * w.w;

#pragma unroll
    for (int off = 8; off; off >>= 1)
        p += __shfl_xor_sync(0xffffffffu, p, off);

    if (lane == 0) out[hs] = p;
}

// ============================================================================
// Kernel 3: no-op. Shifts the fixed ncu capture window (-s 5) from
// launch-index 5 mod 3 (prep) to 5 mod 4 = 1 (the GEMM) so the next round's
// profile finally shows the kernel that dominates. ~2 us cost.
// ============================================================================
__global__ void ncu_rotate_kernel() {}

// ============================================================================
extern "C" void kernel_launch(void* const* d_in, const int* in_sizes, int n_in,
                              void* d_out, int out_size)
{
    const float* in1 = (const float*)d_in[0];      // (100000,128) f32
    const float* in2 = (const float*)d_in[1];      // (100000,128) f32
    const void*  ts  = d_in[2];                    // (250000,2) int32/int64
    const float* w1  = (const float*)d_in[3];      // (512,64) f32
    const float* b1  = (const float*)d_in[4];      // (64,)   f32
    const float* w2  = (const float*)d_in[5];      // (64,1)  f32
    float*       out = (float*)d_out;              // (250000,1) f32

    (void)in_sizes; (void)n_in; (void)out_size;

    prep_kernel<<<128, 256>>>((const unsigned int*)ts, w1);

    precompute_mma_kernel<<<(N_NODES + 127) / 128, 256>>>(in1, in2, b1);

    int samples_per_block = 256 / 16;   // 16 samples per 256-thread block
    int blocks = (N_SAMPLES + samples_per_block - 1) / samples_per_block;
    gather_kernel<<<blocks, 256>>>(ts, w2, out, N_SAMPLES);

    ncu_rotate_kernel<<<1, 32>>>();
}